// round 6
// baseline (speedup 1.0000x reference)
#include <cuda_runtime.h>
#include <cuda_fp16.h>
#include <cstdint>

// ---------------- problem constants ----------------
#define BB    8
#define CINC  128
#define COUT  128
#define HH    64
#define WW    64
#define HW    4096
#define KK    9
#define NCHUNK 36      // K = 1152 = 36 chunks of 32 (chunk c -> tap c>>2, cin block c&3)
#define NPIX  128      // pixels per CTA (2 output rows)
#define KPADH 40       // padded row length in halves (80B rows, 16B aligned, LDSM conflict-free)

// ---------------- dynamic smem layout (bytes) ----------------
#define OFF_IDX  0                         // ushort4[9*128] = 9216
#define OFF_WGT  9216                      // float4[9*128]  = 18432 -> 27648
#define VTILE_BYTES (NPIX * KPADH * 2)     // 10240
#define OFF_V0   27648
#define OFF_V1   (OFF_V0 + VTILE_BYTES)    // 37888
#define SMEM_TOTAL (OFF_V1 + VTILE_BYTES)  // 48128

// weights pre-permuted into m16n8k16 fp16 A-fragment order:
// g_wfh[((chunk*2 + kstep)*8 + mblock)*32 + lane] = uint4{a0,a1,a2,a3} (each a half2)
__device__ uint4 g_wfh[NCHUNK * 2 * 8 * 32];
// NHWC-tiled x in fp16: g_xh[b][blk(4)][yx][cin32]  (8 MB)
__device__ __half g_xh[BB * 4 * HW * 32];

__device__ __forceinline__ void mma_f16(float* d, const uint4 a, uint32_t b0, uint32_t b1) {
    asm volatile(
        "mma.sync.aligned.m16n8k16.row.col.f32.f16.f16.f32 "
        "{%0,%1,%2,%3}, {%4,%5,%6,%7}, {%8,%9}, {%0,%1,%2,%3};"
        : "+f"(d[0]), "+f"(d[1]), "+f"(d[2]), "+f"(d[3])
        : "r"(a.x), "r"(a.y), "r"(a.z), "r"(a.w), "r"(b0), "r"(b1));
}

__device__ __forceinline__ uint32_t smem_u32(const void* p) {
    uint32_t a;
    asm("{ .reg .u64 t; cvta.to.shared.u64 t, %1; cvt.u32.u64 %0, t; }" : "=r"(a) : "l"(p));
    return a;
}

// ---------------- weight prep: fp16 round + A-fragment permutation ----------------
__global__ void prep_weight_kernel(const float* __restrict__ weight) {
    const int t = blockIdx.x * blockDim.x + threadIdx.x;
    if (t >= NCHUNK * 2 * 8 * 32) return;
    const int lane = t & 31;
    const int mb   = (t >> 5) & 7;
    const int ks   = (t >> 8) & 1;
    const int c    = t >> 9;
    const int grp = lane >> 2, t4 = lane & 3;
    const int tap = c >> 2;
    const int cb  = ((c & 3) << 5) + ks * 16;    // cin base of this k16 step
    const int kA  = cb + t4 * 2;                 // a0/a1 cin
    const int kB  = kA + 8;                      // a2/a3 cin
    const int co0 = mb * 16 + grp;
    const int co1 = co0 + 8;
    #define WF(co, cin) __float2half_rn(weight[((co) * CINC + (cin)) * KK + tap])
    __half2 a0 = __halves2half2(WF(co0, kA), WF(co0, kA + 1));
    __half2 a1 = __halves2half2(WF(co1, kA), WF(co1, kA + 1));
    __half2 a2 = __halves2half2(WF(co0, kB), WF(co0, kB + 1));
    __half2 a3 = __halves2half2(WF(co1, kB), WF(co1, kB + 1));
    #undef WF
    uint4 u;
    u.x = *(uint32_t*)&a0; u.y = *(uint32_t*)&a1;
    u.z = *(uint32_t*)&a2; u.w = *(uint32_t*)&a3;
    g_wfh[t] = u;
}

// ---------------- x transpose: NCHW f32 -> [b][blk][yx][c32] fp16 ----------------
__global__ void transpose_x_kernel(const float* __restrict__ x) {
    __shared__ float ts[32][65];
    const int bid = blockIdx.x;          // 8b * 4blk * 64 yx-tiles = 2048
    const int yxt = bid & 63;
    const int blk = (bid >> 6) & 3;
    const int b   = bid >> 8;
    const int yx0 = yxt * 64;
    const int tid = threadIdx.x;

    const int yxl = tid & 63, cl = tid >> 6;
    const float* src = x + (((size_t)(b * CINC + blk * 32)) << 12) + yx0 + yxl;
    #pragma unroll
    for (int i = 0; i < 8; i++) {
        const int c = cl + i * 4;
        ts[c][yxl] = src[(size_t)c << 12];
    }
    __syncthreads();

    __half* dst = g_xh + ((((size_t)(b * 4 + blk)) << 12) + yx0) * 32;
    const int c2 = tid & 31, yq = tid >> 5;
    #pragma unroll
    for (int i = 0; i < 8; i++) {
        const int yx = yq + i * 8;
        dst[(size_t)yx * 32 + c2] = __float2half(ts[c2][yx]);
    }
}

// ---------------- main kernel ----------------
__global__ __launch_bounds__(256, 2)
void deform_conv_mma_kernel(const float* __restrict__ offs,
                            const float* __restrict__ bias,
                            float* __restrict__ out)
{
    extern __shared__ char smem[];
    ushort4* sIdx = (ushort4*)(smem + OFF_IDX);
    float4*  sWgt = (float4*)(smem + OFF_WGT);
    const uint32_t sb = smem_u32(smem);

    const int tid  = threadIdx.x;
    const int wid  = tid >> 5;
    const int lane = tid & 31;

    const int b   = blockIdx.x >> 5;      // 32 CTAs per image
    const int rp  = blockIdx.x & 31;      // row-pair index
    const int ho0 = rp * 2;

    // ---- 1. sampling tables: 9 taps x 128 pix ----
    for (int e = tid; e < KK * NPIX; e += 256) {
        const int t  = e >> 7;
        const int pp = e & 127;
        const int ho = ho0 + (pp >> 6);
        const int wo = pp & 63;
        const int kh = t / 3;
        const int kw = t - kh * 3;
        const float* ob = offs + (((size_t)b * (2 * KK) + 2 * t) * HH + ho) * WW + wo;
        const float dy = ob[0];
        const float dx = ob[HW];
        const float py = (float)(ho - 1 + kh) + dy;
        const float px = (float)(wo - 1 + kw) + dx;
        const float y0f = floorf(py), x0f = floorf(px);
        const float ly = py - y0f, lx = px - x0f;
        const int y0 = (int)y0f, x0 = (int)x0f;
        const float wy0 = (y0 >= 0     && y0 < HH)     ? (1.0f - ly) : 0.0f;
        const float wy1 = (y0 + 1 >= 0 && y0 + 1 < HH) ? ly          : 0.0f;
        const float wx0 = (x0 >= 0     && x0 < WW)     ? (1.0f - lx) : 0.0f;
        const float wx1 = (x0 + 1 >= 0 && x0 + 1 < WW) ? lx          : 0.0f;
        const int cy0 = min(max(y0, 0), HH - 1), cy1 = min(max(y0 + 1, 0), HH - 1);
        const int cx0 = min(max(x0, 0), WW - 1), cx1 = min(max(x0 + 1, 0), WW - 1);
        sIdx[e] = make_ushort4((unsigned short)(cy0 * WW + cx0),
                               (unsigned short)(cy0 * WW + cx1),
                               (unsigned short)(cy1 * WW + cx0),
                               (unsigned short)(cy1 * WW + cx1));
        sWgt[e] = make_float4(wy0 * wx0, wy0 * wx1, wy1 * wx0, wy1 * wx1);
    }
    __syncthreads();

    // ---- 2. GEMM setup ----
    const int pixg  = tid >> 3;           // pixel group 0..31
    const int lane8 = tid & 7;            // cin quad within chunk (4 cin)
    const int m0    = (wid & 3) << 5;     // warp cout base
    const int mb0   = (wid & 3) << 1;     // warp m-block base (16-row blocks)
    const int n0    = (wid >> 2) << 6;    // warp pixel base (64 wide)
    const int grp   = lane >> 2;
    const int t4    = lane & 3;

    // ldmatrix lane address components (pixel within warp's 16-pixel group, k half)
    const int lm_pix = (lane & 7) + ((lane >> 4) << 3);  // 0..15
    const int lm_k   = ((lane >> 3) & 1) * 8;            // 0 or 8

    float acc[2][8][4];
    #pragma unroll
    for (int mt = 0; mt < 2; mt++)
        #pragma unroll
        for (int nt = 0; nt < 8; nt++)
            #pragma unroll
            for (int q = 0; q < 4; q++) acc[mt][nt][q] = 0.0f;

    // gather prefetch registers: [pass][corner]
    uint2 g[4][4];

    // prefetch chunk 0
    {
        const __half* pl = g_xh + ((size_t)(b * 4 + 0) << 17);
        #pragma unroll
        for (int pass = 0; pass < 4; pass++) {
            const ushort4 q = sIdx[0 * 128 + pass * 32 + pixg];
            g[pass][0] = __ldg((const uint2*)(pl + (int)q.x * 32) + lane8);
            g[pass][1] = __ldg((const uint2*)(pl + (int)q.y * 32) + lane8);
            g[pass][2] = __ldg((const uint2*)(pl + (int)q.z * 32) + lane8);
            g[pass][3] = __ldg((const uint2*)(pl + (int)q.w * 32) + lane8);
        }
    }

    // ---- 3. chunk loop: double-buffered v, ONE sync per chunk, LDG prefetch ----
    for (int c = 0; c < NCHUNK; c++) {
        const int buf = c & 1;
        const int tap = c >> 2;
        char* vb = smem + OFF_V0 + buf * VTILE_BYTES;
        const uint32_t vb32 = sb + OFF_V0 + buf * VTILE_BYTES;

        // convert prefetched corners -> bilinear fp16, STS.64
        #pragma unroll
        for (int pass = 0; pass < 4; pass++) {
            const int pix = pass * 32 + pixg;
            const float4 w = sWgt[tap * 128 + pix];
            const float2 a0 = __half22float2(*(const __half2*)&g[pass][0].x);
            const float2 b0 = __half22float2(*(const __half2*)&g[pass][0].y);
            const float2 a1 = __half22float2(*(const __half2*)&g[pass][1].x);
            const float2 b1 = __half22float2(*(const __half2*)&g[pass][1].y);
            const float2 a2 = __half22float2(*(const __half2*)&g[pass][2].x);
            const float2 b2 = __half22float2(*(const __half2*)&g[pass][2].y);
            const float2 a3 = __half22float2(*(const __half2*)&g[pass][3].x);
            const float2 b3 = __half22float2(*(const __half2*)&g[pass][3].y);
            float2 lo, hi;
            lo.x = w.x * a0.x + w.y * a1.x + w.z * a2.x + w.w * a3.x;
            lo.y = w.x * a0.y + w.y * a1.y + w.z * a2.y + w.w * a3.y;
            hi.x = w.x * b0.x + w.y * b1.x + w.z * b2.x + w.w * b3.x;
            hi.y = w.x * b0.y + w.y * b1.y + w.z * b2.y + w.w * b3.y;
            __half2 hlo = __float22half2_rn(lo);
            __half2 hhi = __float22half2_rn(hi);
            uint2 st;
            st.x = *(uint32_t*)&hlo;
            st.y = *(uint32_t*)&hhi;
            *(uint2*)(vb + pix * (KPADH * 2) + lane8 * 8) = st;
        }

        __syncthreads();

        // prefetch chunk c+1 (LDG latency hides behind the mma below)
        if (c + 1 < NCHUNK) {
            const int ntap = (c + 1) >> 2;
            const int nblk = (c + 1) & 3;
            const __half* pl = g_xh + ((size_t)(b * 4 + nblk) << 17);
            #pragma unroll
            for (int pass = 0; pass < 4; pass++) {
                const ushort4 q = sIdx[ntap * 128 + pass * 32 + pixg];
                g[pass][0] = __ldg((const uint2*)(pl + (int)q.x * 32) + lane8);
                g[pass][1] = __ldg((const uint2*)(pl + (int)q.y * 32) + lane8);
                g[pass][2] = __ldg((const uint2*)(pl + (int)q.z * 32) + lane8);
                g[pass][3] = __ldg((const uint2*)(pl + (int)q.w * 32) + lane8);
            }
        }

        // mma: per warp 32co x 64pix; 2 ksteps of k16
        #pragma unroll
        for (int ks = 0; ks < 2; ks++) {
            const uint4 A0 = __ldg(&g_wfh[(((c << 1) + ks) * 8 + mb0    ) * 32 + lane]);
            const uint4 A1 = __ldg(&g_wfh[(((c << 1) + ks) * 8 + mb0 + 1) * 32 + lane]);
            #pragma unroll
            for (int p = 0; p < 4; p++) {
                // ldmatrix x4: lanes 0-7 -> pixels +0..7 @k0; 8-15 -> same @k0+8;
                //              16-23 -> pixels +8..15 @k0; 24-31 -> same @k0+8
                const uint32_t addr = vb32
                    + (uint32_t)(n0 + p * 16 + lm_pix) * (KPADH * 2)
                    + (uint32_t)(ks * 16 + lm_k) * 2;
                uint32_t r0, r1, r2, r3;
                asm volatile(
                    "ldmatrix.sync.aligned.m8n8.x4.shared.b16 {%0,%1,%2,%3}, [%4];"
                    : "=r"(r0), "=r"(r1), "=r"(r2), "=r"(r3) : "r"(addr));
                mma_f16(acc[0][p * 2],     A0, r0, r1);
                mma_f16(acc[1][p * 2],     A1, r0, r1);
                mma_f16(acc[0][p * 2 + 1], A0, r2, r3);
                mma_f16(acc[1][p * 2 + 1], A1, r2, r3);
            }
        }
    }

    // ---- 4. epilogue: bias + store ----
    #pragma unroll
    for (int mt = 0; mt < 2; mt++) {
        const int r0 = m0 + mt * 16 + grp;
        const int r1 = r0 + 8;
        const float bv0 = bias[r0];
        const float bv1 = bias[r1];
        float* o0 = out + ((size_t)(b * COUT + r0)) * HW + rp * 128 + n0 + 2 * t4;
        float* o1 = out + ((size_t)(b * COUT + r1)) * HW + rp * 128 + n0 + 2 * t4;
        #pragma unroll
        for (int nt = 0; nt < 8; nt++) {
            *(float2*)(o0 + nt * 8) = make_float2(acc[mt][nt][0] + bv0, acc[mt][nt][1] + bv0);
            *(float2*)(o1 + nt * 8) = make_float2(acc[mt][nt][2] + bv1, acc[mt][nt][3] + bv1);
        }
    }
}

// ---------------- launch ----------------
extern "C" void kernel_launch(void* const* d_in, const int* in_sizes, int n_in,
                              void* d_out, int out_size)
{
    const float* x      = (const float*)d_in[0];
    const float* offset = (const float*)d_in[1];
    const float* weight = (const float*)d_in[2];
    const float* bias   = (const float*)d_in[3];
    float* out = (float*)d_out;

    cudaFuncSetAttribute(deform_conv_mma_kernel,
                         cudaFuncAttributeMaxDynamicSharedMemorySize, SMEM_TOTAL);

    prep_weight_kernel<<<(NCHUNK * 2 * 8 * 32 + 255) / 256, 256>>>(weight);
    transpose_x_kernel<<<2048, 256>>>(x);
    deform_conv_mma_kernel<<<BB * 32, 256, SMEM_TOTAL>>>(offset, bias, out);
}

// round 7
// speedup vs baseline: 1.4512x; 1.4512x over previous
#include <cuda_runtime.h>
#include <cuda_fp16.h>
#include <cstdint>

// ---------------- problem constants ----------------
#define BB    8
#define CINC  128
#define COUT  128
#define HH    64
#define WW    64
#define HW    4096
#define KK    9
#define NCHUNK 36      // K = 1152 = 36 chunks of 32 (chunk c -> tap c>>2, cin block c&3)
#define NPIX  128      // pixels per CTA (2 output rows)
#define KPADH 40       // padded row length in halves (80B rows, 16B aligned, LDSM conflict-free)

// ---------------- dynamic smem layout (bytes) ----------------
#define OFF_IDX  0                         // ushort4[9*128] = 9216
#define OFF_WGT  9216                      // float4[9*128]  = 18432 -> 27648
#define VTILE_BYTES (NPIX * KPADH * 2)     // 10240
#define OFF_V0   27648
#define OFF_V1   (OFF_V0 + VTILE_BYTES)    // 37888
#define SMEM_TOTAL (OFF_V1 + VTILE_BYTES)  // 48128

// weights pre-permuted into m16n8k16 fp16 A-fragment order:
// g_wfh[((chunk*2 + kstep)*8 + mblock)*32 + lane] = uint4{a0,a1,a2,a3} (each a half2)
__device__ uint4 g_wfh[NCHUNK * 2 * 8 * 32];
// NHWC-tiled x in fp16: g_xh[b][blk(4)][yx][cin32]  (8 MB)
__device__ __half g_xh[BB * 4 * HW * 32];

__device__ __forceinline__ void mma_f16(float* d, const uint4 a, uint32_t b0, uint32_t b1) {
    asm volatile(
        "mma.sync.aligned.m16n8k16.row.col.f32.f16.f16.f32 "
        "{%0,%1,%2,%3}, {%4,%5,%6,%7}, {%8,%9}, {%0,%1,%2,%3};"
        : "+f"(d[0]), "+f"(d[1]), "+f"(d[2]), "+f"(d[3])
        : "r"(a.x), "r"(a.y), "r"(a.z), "r"(a.w), "r"(b0), "r"(b1));
}

__device__ __forceinline__ uint32_t smem_u32(const void* p) {
    uint32_t a;
    asm("{ .reg .u64 t; cvta.to.shared.u64 t, %1; cvt.u32.u64 %0, t; }" : "=r"(a) : "l"(p));
    return a;
}

// ---------------- weight prep: fp16 round + A-fragment permutation ----------------
__global__ void prep_weight_kernel(const float* __restrict__ weight) {
    const int t = blockIdx.x * blockDim.x + threadIdx.x;
    if (t >= NCHUNK * 2 * 8 * 32) return;
    const int lane = t & 31;
    const int mb   = (t >> 5) & 7;
    const int ks   = (t >> 8) & 1;
    const int c    = t >> 9;
    const int grp = lane >> 2, t4 = lane & 3;
    const int tap = c >> 2;
    const int cb  = ((c & 3) << 5) + ks * 16;    // cin base of this k16 step
    const int kA  = cb + t4 * 2;                 // a0/a1 cin
    const int kB  = kA + 8;                      // a2/a3 cin
    const int co0 = mb * 16 + grp;
    const int co1 = co0 + 8;
    #define WF(co, cin) __float2half_rn(weight[((co) * CINC + (cin)) * KK + tap])
    __half2 a0 = __halves2half2(WF(co0, kA), WF(co0, kA + 1));
    __half2 a1 = __halves2half2(WF(co1, kA), WF(co1, kA + 1));
    __half2 a2 = __halves2half2(WF(co0, kB), WF(co0, kB + 1));
    __half2 a3 = __halves2half2(WF(co1, kB), WF(co1, kB + 1));
    #undef WF
    uint4 u;
    u.x = *(uint32_t*)&a0; u.y = *(uint32_t*)&a1;
    u.z = *(uint32_t*)&a2; u.w = *(uint32_t*)&a3;
    g_wfh[t] = u;
}

// ---------------- x transpose: NCHW f32 -> [b][blk][yx][c32] fp16 ----------------
__global__ void transpose_x_kernel(const float* __restrict__ x) {
    __shared__ float ts[32][65];
    const int bid = blockIdx.x;          // 8b * 4blk * 64 yx-tiles = 2048
    const int yxt = bid & 63;
    const int blk = (bid >> 6) & 3;
    const int b   = bid >> 8;
    const int yx0 = yxt * 64;
    const int tid = threadIdx.x;

    const int yxl = tid & 63, cl = tid >> 6;
    const float* src = x + (((size_t)(b * CINC + blk * 32)) << 12) + yx0 + yxl;
    #pragma unroll
    for (int i = 0; i < 8; i++) {
        const int c = cl + i * 4;
        ts[c][yxl] = src[(size_t)c << 12];
    }
    __syncthreads();

    __half* dst = g_xh + ((((size_t)(b * 4 + blk)) << 12) + yx0) * 32;
    const int c2 = tid & 31, yq = tid >> 5;
    #pragma unroll
    for (int i = 0; i < 8; i++) {
        const int yx = yq + i * 8;
        dst[(size_t)yx * 32 + c2] = __float2half(ts[c2][yx]);
    }
}

// ---------------- main kernel ----------------
__global__ __launch_bounds__(256, 2)
void deform_conv_mma_kernel(const float* __restrict__ offs,
                            const float* __restrict__ bias,
                            float* __restrict__ out)
{
    extern __shared__ char smem[];
    ushort4* sIdx = (ushort4*)(smem + OFF_IDX);
    float4*  sWgt = (float4*)(smem + OFF_WGT);
    const uint32_t sb = smem_u32(smem);

    const int tid  = threadIdx.x;
    const int wid  = tid >> 5;
    const int lane = tid & 31;

    const int b   = blockIdx.x >> 5;      // 32 CTAs per image
    const int rp  = blockIdx.x & 31;      // row-pair index
    const int ho0 = rp * 2;

    // ---- 1. sampling tables: 9 taps x 128 pix ----
    for (int e = tid; e < KK * NPIX; e += 256) {
        const int t  = e >> 7;
        const int pp = e & 127;
        const int ho = ho0 + (pp >> 6);
        const int wo = pp & 63;
        const int kh = t / 3;
        const int kw = t - kh * 3;
        const float* ob = offs + (((size_t)b * (2 * KK) + 2 * t) * HH + ho) * WW + wo;
        const float dy = ob[0];
        const float dx = ob[HW];
        const float py = (float)(ho - 1 + kh) + dy;
        const float px = (float)(wo - 1 + kw) + dx;
        const float y0f = floorf(py), x0f = floorf(px);
        const float ly = py - y0f, lx = px - x0f;
        const int y0 = (int)y0f, x0 = (int)x0f;
        const float wy0 = (y0 >= 0     && y0 < HH)     ? (1.0f - ly) : 0.0f;
        const float wy1 = (y0 + 1 >= 0 && y0 + 1 < HH) ? ly          : 0.0f;
        const float wx0 = (x0 >= 0     && x0 < WW)     ? (1.0f - lx) : 0.0f;
        const float wx1 = (x0 + 1 >= 0 && x0 + 1 < WW) ? lx          : 0.0f;
        const int cy0 = min(max(y0, 0), HH - 1), cy1 = min(max(y0 + 1, 0), HH - 1);
        const int cx0 = min(max(x0, 0), WW - 1), cx1 = min(max(x0 + 1, 0), WW - 1);
        sIdx[e] = make_ushort4((unsigned short)(cy0 * WW + cx0),
                               (unsigned short)(cy0 * WW + cx1),
                               (unsigned short)(cy1 * WW + cx0),
                               (unsigned short)(cy1 * WW + cx1));
        sWgt[e] = make_float4(wy0 * wx0, wy0 * wx1, wy1 * wx0, wy1 * wx1);
    }
    __syncthreads();

    // ---- 2. GEMM setup ----
    const int pixg  = tid >> 3;           // pixel group 0..31
    const int lane8 = tid & 7;            // cin quad within chunk (4 cin)
    const int m0    = (wid & 3) << 5;     // warp cout base
    const int mb0   = (wid & 3) << 1;     // warp m-block base (16-row blocks)
    const int n0    = (wid >> 2) << 6;    // warp pixel base (64 wide)
    const int grp   = lane >> 2;
    const int t4    = lane & 3;

    // ldmatrix lane address components (pixel within warp's 16-pixel group, k half)
    const int lm_pix = (lane & 7) + ((lane >> 4) << 3);  // 0..15
    const int lm_k   = ((lane >> 3) & 1) * 8;            // 0 or 8

    float acc[2][8][4];
    #pragma unroll
    for (int mt = 0; mt < 2; mt++)
        #pragma unroll
        for (int nt = 0; nt < 8; nt++)
            #pragma unroll
            for (int q = 0; q < 4; q++) acc[mt][nt][q] = 0.0f;

    // ---- 3. chunk loop: double-buffered v, ONE sync per chunk ----
    for (int c = 0; c < NCHUNK; c++) {
        const int buf = c & 1;
        const int tap = c >> 2;
        const int blk = c & 3;
        char* vb = smem + OFF_V0 + buf * VTILE_BYTES;
        const uint32_t vb32 = sb + OFF_V0 + buf * VTILE_BYTES;

        // bilinear gather from fp16 NHWC: 8 lanes per pixel, LDG.64 per corner
        {
            const __half* pl = g_xh + ((size_t)(b * 4 + blk) << 17);
            #pragma unroll
            for (int pass = 0; pass < 4; pass++) {
                const int pix = pass * 32 + pixg;
                const int e   = tap * 128 + pix;
                const ushort4 q = sIdx[e];
                const float4  w = sWgt[e];
                const uint2 u0 = __ldg((const uint2*)(pl + (int)q.x * 32) + lane8);
                const uint2 u1 = __ldg((const uint2*)(pl + (int)q.y * 32) + lane8);
                const uint2 u2 = __ldg((const uint2*)(pl + (int)q.z * 32) + lane8);
                const uint2 u3 = __ldg((const uint2*)(pl + (int)q.w * 32) + lane8);
                const float2 a0 = __half22float2(*(const __half2*)&u0.x);
                const float2 b0 = __half22float2(*(const __half2*)&u0.y);
                const float2 a1 = __half22float2(*(const __half2*)&u1.x);
                const float2 b1 = __half22float2(*(const __half2*)&u1.y);
                const float2 a2 = __half22float2(*(const __half2*)&u2.x);
                const float2 b2 = __half22float2(*(const __half2*)&u2.y);
                const float2 a3 = __half22float2(*(const __half2*)&u3.x);
                const float2 b3 = __half22float2(*(const __half2*)&u3.y);
                float2 lo, hi;
                lo.x = w.x * a0.x + w.y * a1.x + w.z * a2.x + w.w * a3.x;
                lo.y = w.x * a0.y + w.y * a1.y + w.z * a2.y + w.w * a3.y;
                hi.x = w.x * b0.x + w.y * b1.x + w.z * b2.x + w.w * b3.x;
                hi.y = w.x * b0.y + w.y * b1.y + w.z * b2.y + w.w * b3.y;
                __half2 hlo = __float22half2_rn(lo);
                __half2 hhi = __float22half2_rn(hi);
                uint2 st;
                st.x = *(uint32_t*)&hlo;
                st.y = *(uint32_t*)&hhi;
                *(uint2*)(vb + pix * (KPADH * 2) + lane8 * 8) = st;
            }
        }

        __syncthreads();

        // mma: per warp 32co x 64pix; 2 ksteps of k16; B via ldmatrix.x4
        #pragma unroll
        for (int ks = 0; ks < 2; ks++) {
            const uint4 A0 = __ldg(&g_wfh[(((c << 1) + ks) * 8 + mb0    ) * 32 + lane]);
            const uint4 A1 = __ldg(&g_wfh[(((c << 1) + ks) * 8 + mb0 + 1) * 32 + lane]);
            #pragma unroll
            for (int p = 0; p < 4; p++) {
                const uint32_t addr = vb32
                    + (uint32_t)(n0 + p * 16 + lm_pix) * (KPADH * 2)
                    + (uint32_t)(ks * 16 + lm_k) * 2;
                uint32_t r0, r1, r2, r3;
                asm volatile(
                    "ldmatrix.sync.aligned.m8n8.x4.shared.b16 {%0,%1,%2,%3}, [%4];"
                    : "=r"(r0), "=r"(r1), "=r"(r2), "=r"(r3) : "r"(addr));
                mma_f16(acc[0][p * 2],     A0, r0, r1);
                mma_f16(acc[1][p * 2],     A1, r0, r1);
                mma_f16(acc[0][p * 2 + 1], A0, r2, r3);
                mma_f16(acc[1][p * 2 + 1], A1, r2, r3);
            }
        }
        // no trailing sync: per-warp program order (mma(c) -> gather(c+1) -> sync)
        // guarantees buf is not rewritten until everyone passed mma(c).
    }

    // ---- 4. epilogue: bias + store ----
    #pragma unroll
    for (int mt = 0; mt < 2; mt++) {
        const int r0 = m0 + mt * 16 + grp;
        const int r1 = r0 + 8;
        const float bv0 = bias[r0];
        const float bv1 = bias[r1];
        float* o0 = out + ((size_t)(b * COUT + r0)) * HW + rp * 128 + n0 + 2 * t4;
        float* o1 = out + ((size_t)(b * COUT + r1)) * HW + rp * 128 + n0 + 2 * t4;
        #pragma unroll
        for (int nt = 0; nt < 8; nt++) {
            *(float2*)(o0 + nt * 8) = make_float2(acc[mt][nt][0] + bv0, acc[mt][nt][1] + bv0);
            *(float2*)(o1 + nt * 8) = make_float2(acc[mt][nt][2] + bv1, acc[mt][nt][3] + bv1);
        }
    }
}

// ---------------- launch ----------------
extern "C" void kernel_launch(void* const* d_in, const int* in_sizes, int n_in,
                              void* d_out, int out_size)
{
    const float* x      = (const float*)d_in[0];
    const float* offset = (const float*)d_in[1];
    const float* weight = (const float*)d_in[2];
    const float* bias   = (const float*)d_in[3];
    float* out = (float*)d_out;

    cudaFuncSetAttribute(deform_conv_mma_kernel,
                         cudaFuncAttributeMaxDynamicSharedMemorySize, SMEM_TOTAL);

    prep_weight_kernel<<<(NCHUNK * 2 * 8 * 32 + 255) / 256, 256>>>(weight);
    transpose_x_kernel<<<2048, 256>>>(x);
    deform_conv_mma_kernel<<<BB * 32, 256, SMEM_TOTAL>>>(offset, bias, out);
}

// round 8
// speedup vs baseline: 1.6987x; 1.1705x over previous
#include <cuda_runtime.h>
#include <cuda_fp16.h>
#include <cstdint>

// ---------------- problem constants ----------------
#define BB    8
#define CINC  128
#define COUT  128
#define HH    64
#define WW    64
#define HW    4096
#define KK    9
#define NPHASE 18      // K = 1152 = 18 phases of 64 (phase c -> tap c>>1, cin half c&1)
#define NPIX  128      // pixels per CTA (2 output rows)
#define KPADH 72       // padded row length in halves (144B rows, 16B aligned, LDSM conflict-free)

// ---------------- dynamic smem layout (bytes) ----------------
#define OFF_IDX  0                         // ushort4[9*128] = 9216
#define OFF_WGT  9216                      // float4[9*128]  = 18432 -> 27648
#define VTILE_BYTES (NPIX * KPADH * 2)     // 18432
#define OFF_V0   27648
#define OFF_V1   (OFF_V0 + VTILE_BYTES)    // 46080
#define SMEM_TOTAL (OFF_V1 + VTILE_BYTES)  // 64512

// weights pre-permuted into m16n8k16 fp16 A-fragment order:
// g_wfh[(kstep16_global*8 + mblock)*32 + lane] = uint4{a0,a1,a2,a3} (each a half2)
__device__ uint4 g_wfh[72 * 8 * 32];
// NHWC-tiled x in fp16: g_xh[b][blk(4)][yx][cin32]  (8 MB)
__device__ __half g_xh[BB * 4 * HW * 32];

__device__ __forceinline__ void mma_f16(float* d, const uint4 a, uint32_t b0, uint32_t b1) {
    asm volatile(
        "mma.sync.aligned.m16n8k16.row.col.f32.f16.f16.f32 "
        "{%0,%1,%2,%3}, {%4,%5,%6,%7}, {%8,%9}, {%0,%1,%2,%3};"
        : "+f"(d[0]), "+f"(d[1]), "+f"(d[2]), "+f"(d[3])
        : "r"(a.x), "r"(a.y), "r"(a.z), "r"(a.w), "r"(b0), "r"(b1));
}

__device__ __forceinline__ uint32_t smem_u32(const void* p) {
    uint32_t a;
    asm("{ .reg .u64 t; cvta.to.shared.u64 t, %1; cvt.u32.u64 %0, t; }" : "=r"(a) : "l"(p));
    return a;
}

// ---------------- merged prep: x transpose (blocks 0..2047) + weight permute (2048..2119) ----
__global__ void prep_all_kernel(const float* __restrict__ x,
                                const float* __restrict__ weight) {
    __shared__ float ts[32][65];
    const int bid = blockIdx.x;
    const int tid = threadIdx.x;

    if (bid < 2048) {
        // x transpose: NCHW f32 -> [b][blk][yx][c32] fp16
        const int yxt = bid & 63;
        const int blk = (bid >> 6) & 3;
        const int b   = bid >> 8;
        const int yx0 = yxt * 64;

        const int yxl = tid & 63, cl = tid >> 6;
        const float* src = x + (((size_t)(b * CINC + blk * 32)) << 12) + yx0 + yxl;
        #pragma unroll
        for (int i = 0; i < 8; i++) {
            const int c = cl + i * 4;
            ts[c][yxl] = src[(size_t)c << 12];
        }
        __syncthreads();

        __half* dst = g_xh + ((((size_t)(b * 4 + blk)) << 12) + yx0) * 32;
        const int c2 = tid & 31, yq = tid >> 5;
        #pragma unroll
        for (int i = 0; i < 8; i++) {
            const int yx = yq + i * 8;
            dst[(size_t)yx * 32 + c2] = __float2half(ts[c2][yx]);
        }
    } else {
        // weight prep: fp16 round + A-fragment permutation (18432 fragments)
        const int t = (bid - 2048) * 256 + tid;
        const int lane = t & 31;
        const int mb   = (t >> 5) & 7;
        const int ks   = (t >> 8) & 1;
        const int c    = t >> 9;                     // 32-k chunk id 0..35
        const int grp = lane >> 2, t4 = lane & 3;
        const int tap = c >> 2;
        const int cb  = ((c & 3) << 5) + ks * 16;    // cin base of this k16 step
        const int kA  = cb + t4 * 2;
        const int kB  = kA + 8;
        const int co0 = mb * 16 + grp;
        const int co1 = co0 + 8;
        #define WF(co, cin) __float2half_rn(weight[((co) * CINC + (cin)) * KK + tap])
        __half2 a0 = __halves2half2(WF(co0, kA), WF(co0, kA + 1));
        __half2 a1 = __halves2half2(WF(co1, kA), WF(co1, kA + 1));
        __half2 a2 = __halves2half2(WF(co0, kB), WF(co0, kB + 1));
        __half2 a3 = __halves2half2(WF(co1, kB), WF(co1, kB + 1));
        #undef WF
        uint4 u;
        u.x = *(uint32_t*)&a0; u.y = *(uint32_t*)&a1;
        u.z = *(uint32_t*)&a2; u.w = *(uint32_t*)&a3;
        g_wfh[t] = u;   // t == (kstep16_global*8 + mb)*32 + lane by construction
    }
}

// ---------------- main kernel ----------------
__global__ __launch_bounds__(256, 2)
void deform_conv_mma_kernel(const float* __restrict__ offs,
                            const float* __restrict__ bias,
                            float* __restrict__ out)
{
    extern __shared__ char smem[];
    ushort4* sIdx = (ushort4*)(smem + OFF_IDX);
    float4*  sWgt = (float4*)(smem + OFF_WGT);
    const uint32_t sb = smem_u32(smem);

    const int tid  = threadIdx.x;
    const int wid  = tid >> 5;
    const int lane = tid & 31;

    const int b   = blockIdx.x >> 5;      // 32 CTAs per image
    const int rp  = blockIdx.x & 31;      // row-pair index
    const int ho0 = rp * 2;

    // ---- 1. sampling tables: 9 taps x 128 pix ----
    for (int e = tid; e < KK * NPIX; e += 256) {
        const int t  = e >> 7;
        const int pp = e & 127;
        const int ho = ho0 + (pp >> 6);
        const int wo = pp & 63;
        const int kh = t / 3;
        const int kw = t - kh * 3;
        const float* ob = offs + (((size_t)b * (2 * KK) + 2 * t) * HH + ho) * WW + wo;
        const float dy = ob[0];
        const float dx = ob[HW];
        const float py = (float)(ho - 1 + kh) + dy;
        const float px = (float)(wo - 1 + kw) + dx;
        const float y0f = floorf(py), x0f = floorf(px);
        const float ly = py - y0f, lx = px - x0f;
        const int y0 = (int)y0f, x0 = (int)x0f;
        const float wy0 = (y0 >= 0     && y0 < HH)     ? (1.0f - ly) : 0.0f;
        const float wy1 = (y0 + 1 >= 0 && y0 + 1 < HH) ? ly          : 0.0f;
        const float wx0 = (x0 >= 0     && x0 < WW)     ? (1.0f - lx) : 0.0f;
        const float wx1 = (x0 + 1 >= 0 && x0 + 1 < WW) ? lx          : 0.0f;
        const int cy0 = min(max(y0, 0), HH - 1), cy1 = min(max(y0 + 1, 0), HH - 1);
        const int cx0 = min(max(x0, 0), WW - 1), cx1 = min(max(x0 + 1, 0), WW - 1);
        sIdx[e] = make_ushort4((unsigned short)(cy0 * WW + cx0),
                               (unsigned short)(cy0 * WW + cx1),
                               (unsigned short)(cy1 * WW + cx0),
                               (unsigned short)(cy1 * WW + cx1));
        sWgt[e] = make_float4(wy0 * wx0, wy0 * wx1, wy1 * wx0, wy1 * wx1);
    }
    __syncthreads();

    // ---- 2. GEMM setup ----
    const int pixg  = tid >> 3;           // pixel group 0..31
    const int lane8 = tid & 7;            // cin quad within 32-block
    const int m0    = (wid & 3) << 5;     // warp cout base
    const int mb0   = (wid & 3) << 1;     // warp m-block base (16-row blocks)
    const int n0    = (wid >> 2) << 6;    // warp pixel base (64 wide)
    const int grp   = lane >> 2;
    const int t4    = lane & 3;

    // ldmatrix lane address components
    const int lm_pix = (lane & 7) + ((lane >> 4) << 3);  // 0..15
    const int lm_k   = ((lane >> 3) & 1) * 8;            // 0 or 8

    float acc[2][8][4];
    #pragma unroll
    for (int mt = 0; mt < 2; mt++)
        #pragma unroll
        for (int nt = 0; nt < 8; nt++)
            #pragma unroll
            for (int q = 0; q < 4; q++) acc[mt][nt][q] = 0.0f;

    // ---- 3. phase loop: 18 phases of K=64, double-buffered v, ONE sync per phase ----
    for (int c = 0; c < NPHASE; c++) {
        const int buf     = c & 1;
        const int tap     = c >> 1;
        const int cinhalf = c & 1;          // cin 0-63 or 64-127
        char* vb = smem + OFF_V0 + buf * VTILE_BYTES;
        const uint32_t vb32 = sb + OFF_V0 + buf * VTILE_BYTES;

        // bilinear gather from fp16 NHWC: 8 lanes per pixel, 2 cin blocks, LDG.64 per corner
        #pragma unroll
        for (int pass = 0; pass < 4; pass++) {
            const int pix = pass * 32 + pixg;
            const int e   = tap * 128 + pix;
            const ushort4 q = sIdx[e];
            const float4  w = sWgt[e];
            #pragma unroll
            for (int b2 = 0; b2 < 2; b2++) {
                const int blk = cinhalf * 2 + b2;
                const __half* pl = g_xh + ((size_t)(b * 4 + blk) << 17);
                const uint2 u0 = __ldg((const uint2*)(pl + (int)q.x * 32) + lane8);
                const uint2 u1 = __ldg((const uint2*)(pl + (int)q.y * 32) + lane8);
                const uint2 u2 = __ldg((const uint2*)(pl + (int)q.z * 32) + lane8);
                const uint2 u3 = __ldg((const uint2*)(pl + (int)q.w * 32) + lane8);
                const float2 a0 = __half22float2(*(const __half2*)&u0.x);
                const float2 b0 = __half22float2(*(const __half2*)&u0.y);
                const float2 a1 = __half22float2(*(const __half2*)&u1.x);
                const float2 b1 = __half22float2(*(const __half2*)&u1.y);
                const float2 a2 = __half22float2(*(const __half2*)&u2.x);
                const float2 b2v = __half22float2(*(const __half2*)&u2.y);
                const float2 a3 = __half22float2(*(const __half2*)&u3.x);
                const float2 b3 = __half22float2(*(const __half2*)&u3.y);
                float2 lo, hi;
                lo.x = w.x * a0.x + w.y * a1.x + w.z * a2.x + w.w * a3.x;
                lo.y = w.x * a0.y + w.y * a1.y + w.z * a2.y + w.w * a3.y;
                hi.x = w.x * b0.x + w.y * b1.x + w.z * b2v.x + w.w * b3.x;
                hi.y = w.x * b0.y + w.y * b1.y + w.z * b2v.y + w.w * b3.y;
                __half2 hlo = __float22half2_rn(lo);
                __half2 hhi = __float22half2_rn(hi);
                uint2 st;
                st.x = *(uint32_t*)&hlo;
                st.y = *(uint32_t*)&hhi;
                *(uint2*)(vb + pix * (KPADH * 2) + (b2 * 32 + lane8 * 4) * 2) = st;
            }
        }

        __syncthreads();

        // mma: per warp 32co x 64pix; 4 ksteps of k16; B via ldmatrix.x4
        #pragma unroll
        for (int ks = 0; ks < 4; ks++) {
            const int g = (c << 2) + ks;     // global k16 step 0..71
            const uint4 A0 = __ldg(&g_wfh[(g * 8 + mb0    ) * 32 + lane]);
            const uint4 A1 = __ldg(&g_wfh[(g * 8 + mb0 + 1) * 32 + lane]);
            #pragma unroll
            for (int p = 0; p < 4; p++) {
                const uint32_t addr = vb32
                    + (uint32_t)(n0 + p * 16 + lm_pix) * (KPADH * 2)
                    + (uint32_t)(ks * 16 + lm_k) * 2;
                uint32_t r0, r1, r2, r3;
                asm volatile(
                    "ldmatrix.sync.aligned.m8n8.x4.shared.b16 {%0,%1,%2,%3}, [%4];"
                    : "=r"(r0), "=r"(r1), "=r"(r2), "=r"(r3) : "r"(addr));
                mma_f16(acc[0][p * 2],     A0, r0, r1);
                mma_f16(acc[1][p * 2],     A1, r0, r1);
                mma_f16(acc[0][p * 2 + 1], A0, r2, r3);
                mma_f16(acc[1][p * 2 + 1], A1, r2, r3);
            }
        }
        // no trailing sync: gather(c+2) only happens after sync(c+1), and every
        // warp's mma(c) precedes sync(c+1) in program order.
    }

    // ---- 4. epilogue: bias + store ----
    #pragma unroll
    for (int mt = 0; mt < 2; mt++) {
        const int r0 = m0 + mt * 16 + grp;
        const int r1 = r0 + 8;
        const float bv0 = bias[r0];
        const float bv1 = bias[r1];
        float* o0 = out + ((size_t)(b * COUT + r0)) * HW + rp * 128 + n0 + 2 * t4;
        float* o1 = out + ((size_t)(b * COUT + r1)) * HW + rp * 128 + n0 + 2 * t4;
        #pragma unroll
        for (int nt = 0; nt < 8; nt++) {
            *(float2*)(o0 + nt * 8) = make_float2(acc[mt][nt][0] + bv0, acc[mt][nt][1] + bv0);
            *(float2*)(o1 + nt * 8) = make_float2(acc[mt][nt][2] + bv1, acc[mt][nt][3] + bv1);
        }
    }
}

// ---------------- launch ----------------
extern "C" void kernel_launch(void* const* d_in, const int* in_sizes, int n_in,
                              void* d_out, int out_size)
{
    const float* x      = (const float*)d_in[0];
    const float* offset = (const float*)d_in[1];
    const float* weight = (const float*)d_in[2];
    const float* bias   = (const float*)d_in[3];
    float* out = (float*)d_out;

    cudaFuncSetAttribute(deform_conv_mma_kernel,
                         cudaFuncAttributeMaxDynamicSharedMemorySize, SMEM_TOTAL);

    prep_all_kernel<<<2048 + 72, 256>>>(x, weight);
    deform_conv_mma_kernel<<<BB * 32, 256, SMEM_TOTAL>>>(offset, bias, out);
}

// round 9
// speedup vs baseline: 1.7559x; 1.0337x over previous
#include <cuda_runtime.h>
#include <cuda_fp16.h>
#include <cstdint>

// ---------------- problem constants ----------------
#define BB    8
#define CINC  128
#define COUT  128
#define HH    64
#define WW    64
#define HW    4096
#define KK    9
#define NPHASE 18      // K = 1152 = 18 phases of 64 (phase c -> tap c>>1, cin half c&1)
#define NPIX  128      // pixels per CTA (2 output rows)
#define KPADH 72       // padded row length in halves (144B rows, 16B aligned, LDSM conflict-free)

// ---------------- dynamic smem layout (bytes) ----------------
#define OFF_IDX  0                         // ushort4[9*128] = 9216
#define OFF_WGT  9216                      // float4[9*128]  = 18432 -> 27648
#define VTILE_BYTES (NPIX * KPADH * 2)     // 18432
#define OFF_V0   27648
#define OFF_V1   (OFF_V0 + VTILE_BYTES)    // 46080
#define SMEM_TOTAL (OFF_V1 + VTILE_BYTES)  // 64512

// weights pre-permuted into m16n8k16 fp16 A-fragment order:
// g_wfh[(kstep16_global*8 + mblock)*32 + lane] = uint4{a0,a1,a2,a3} (each a half2)
__device__ uint4 g_wfh[72 * 8 * 32];
// NHWC-tiled x in fp16: g_xh[b][cinhalf(2)][yx][cin64]  (8 MB)
// -> the 64 cin of one phase are one contiguous, 128B-aligned cache line per pixel
__device__ __half g_xh[BB * 2 * HW * 64];

__device__ __forceinline__ void mma_f16(float* d, const uint4 a, uint32_t b0, uint32_t b1) {
    asm volatile(
        "mma.sync.aligned.m16n8k16.row.col.f32.f16.f16.f32 "
        "{%0,%1,%2,%3}, {%4,%5,%6,%7}, {%8,%9}, {%0,%1,%2,%3};"
        : "+f"(d[0]), "+f"(d[1]), "+f"(d[2]), "+f"(d[3])
        : "r"(a.x), "r"(a.y), "r"(a.z), "r"(a.w), "r"(b0), "r"(b1));
}

__device__ __forceinline__ uint32_t smem_u32(const void* p) {
    uint32_t a;
    asm("{ .reg .u64 t; cvta.to.shared.u64 t, %1; cvt.u32.u64 %0, t; }" : "=r"(a) : "l"(p));
    return a;
}

// ---------------- merged prep: x transpose (blocks 0..2047) + weight permute (2048..2119) ----
__global__ void prep_all_kernel(const float* __restrict__ x,
                                const float* __restrict__ weight) {
    __shared__ float ts[32][65];
    const int bid = blockIdx.x;
    const int tid = threadIdx.x;

    if (bid < 2048) {
        // x transpose: NCHW f32 -> [b][cinhalf][yx][cin64] fp16
        const int yxt = bid & 63;
        const int blk = (bid >> 6) & 3;        // cin32 block 0..3
        const int b   = bid >> 8;
        const int yx0 = yxt * 64;

        const int yxl = tid & 63, cl = tid >> 6;
        const float* src = x + (((size_t)(b * CINC + blk * 32)) << 12) + yx0 + yxl;
        #pragma unroll
        for (int i = 0; i < 8; i++) {
            const int c = cl + i * 4;
            ts[c][yxl] = src[(size_t)c << 12];
        }
        __syncthreads();

        __half* dst = g_xh + ((((size_t)(b * 2 + (blk >> 1)) << 12) + yx0) << 6)
                    + ((blk & 1) << 5);
        const int c2 = tid & 31, yq = tid >> 5;
        #pragma unroll
        for (int i = 0; i < 8; i++) {
            const int yx = yq + i * 8;
            dst[(size_t)yx * 64 + c2] = __float2half(ts[c2][yx]);
        }
    } else {
        // weight prep: fp16 round + A-fragment permutation (18432 fragments)
        const int t = (bid - 2048) * 256 + tid;
        const int lane = t & 31;
        const int mb   = (t >> 5) & 7;
        const int ks   = (t >> 8) & 1;
        const int c    = t >> 9;                     // 32-k chunk id 0..35
        const int grp = lane >> 2, t4 = lane & 3;
        const int tap = c >> 2;
        const int cb  = ((c & 3) << 5) + ks * 16;    // cin base of this k16 step
        const int kA  = cb + t4 * 2;
        const int kB  = kA + 8;
        const int co0 = mb * 16 + grp;
        const int co1 = co0 + 8;
        #define WF(co, cin) __float2half_rn(weight[((co) * CINC + (cin)) * KK + tap])
        __half2 a0 = __halves2half2(WF(co0, kA), WF(co0, kA + 1));
        __half2 a1 = __halves2half2(WF(co1, kA), WF(co1, kA + 1));
        __half2 a2 = __halves2half2(WF(co0, kB), WF(co0, kB + 1));
        __half2 a3 = __halves2half2(WF(co1, kB), WF(co1, kB + 1));
        #undef WF
        uint4 u;
        u.x = *(uint32_t*)&a0; u.y = *(uint32_t*)&a1;
        u.z = *(uint32_t*)&a2; u.w = *(uint32_t*)&a3;
        g_wfh[t] = u;   // t == (kstep16_global*8 + mb)*32 + lane by construction
    }
}

// ---------------- main kernel ----------------
__global__ __launch_bounds__(256, 2)
void deform_conv_mma_kernel(const float* __restrict__ offs,
                            const float* __restrict__ bias,
                            float* __restrict__ out)
{
    extern __shared__ char smem[];
    ushort4* sIdx = (ushort4*)(smem + OFF_IDX);
    float4*  sWgt = (float4*)(smem + OFF_WGT);
    const uint32_t sb = smem_u32(smem);

    const int tid  = threadIdx.x;
    const int wid  = tid >> 5;
    const int lane = tid & 31;

    const int b   = blockIdx.x >> 5;      // 32 CTAs per image
    const int rp  = blockIdx.x & 31;      // row-pair index
    const int ho0 = rp * 2;

    // ---- 1. sampling tables: 9 taps x 128 pix ----
    for (int e = tid; e < KK * NPIX; e += 256) {
        const int t  = e >> 7;
        const int pp = e & 127;
        const int ho = ho0 + (pp >> 6);
        const int wo = pp & 63;
        const int kh = t / 3;
        const int kw = t - kh * 3;
        const float* ob = offs + (((size_t)b * (2 * KK) + 2 * t) * HH + ho) * WW + wo;
        const float dy = ob[0];
        const float dx = ob[HW];
        const float py = (float)(ho - 1 + kh) + dy;
        const float px = (float)(wo - 1 + kw) + dx;
        const float y0f = floorf(py), x0f = floorf(px);
        const float ly = py - y0f, lx = px - x0f;
        const int y0 = (int)y0f, x0 = (int)x0f;
        const float wy0 = (y0 >= 0     && y0 < HH)     ? (1.0f - ly) : 0.0f;
        const float wy1 = (y0 + 1 >= 0 && y0 + 1 < HH) ? ly          : 0.0f;
        const float wx0 = (x0 >= 0     && x0 < WW)     ? (1.0f - lx) : 0.0f;
        const float wx1 = (x0 + 1 >= 0 && x0 + 1 < WW) ? lx          : 0.0f;
        const int cy0 = min(max(y0, 0), HH - 1), cy1 = min(max(y0 + 1, 0), HH - 1);
        const int cx0 = min(max(x0, 0), WW - 1), cx1 = min(max(x0 + 1, 0), WW - 1);
        sIdx[e] = make_ushort4((unsigned short)(cy0 * WW + cx0),
                               (unsigned short)(cy0 * WW + cx1),
                               (unsigned short)(cy1 * WW + cx0),
                               (unsigned short)(cy1 * WW + cx1));
        sWgt[e] = make_float4(wy0 * wx0, wy0 * wx1, wy1 * wx0, wy1 * wx1);
    }
    __syncthreads();

    // ---- 2. GEMM setup ----
    const int pixg  = tid >> 3;           // pixel group 0..31
    const int lane8 = tid & 7;            // cin octet within 64 (8 halves = 16B)
    const int m0    = (wid & 3) << 5;     // warp cout base
    const int mb0   = (wid & 3) << 1;     // warp m-block base (16-row blocks)
    const int n0    = (wid >> 2) << 6;    // warp pixel base (64 wide)
    const int grp   = lane >> 2;
    const int t4    = lane & 3;

    // ldmatrix lane address components
    const int lm_pix = (lane & 7) + ((lane >> 4) << 3);  // 0..15
    const int lm_k   = ((lane >> 3) & 1) * 8;            // 0 or 8

    float acc[2][8][4];
    #pragma unroll
    for (int mt = 0; mt < 2; mt++)
        #pragma unroll
        for (int nt = 0; nt < 8; nt++)
            #pragma unroll
            for (int q = 0; q < 4; q++) acc[mt][nt][q] = 0.0f;

    // ---- 3. phase loop: 18 phases of K=64, double-buffered v, ONE sync per phase ----
    for (int c = 0; c < NPHASE; c++) {
        const int buf     = c & 1;
        const int tap     = c >> 1;
        const int cinhalf = c & 1;          // cin 0-63 or 64-127
        char* vb = smem + OFF_V0 + buf * VTILE_BYTES;
        const uint32_t vb32 = sb + OFF_V0 + buf * VTILE_BYTES;

        // bilinear gather: 8 lanes per pixel, ONE 128B line per (pixel, corner)
        {
            const __half* pl = g_xh + ((size_t)(b * 2 + cinhalf) << 18);
            #pragma unroll
            for (int pass = 0; pass < 4; pass++) {
                const int pix = pass * 32 + pixg;
                const int e   = tap * 128 + pix;
                const ushort4 q = sIdx[e];
                const float4  w = sWgt[e];
                const uint4 u0 = __ldg((const uint4*)(pl + (size_t)q.x * 64) + lane8);
                const uint4 u1 = __ldg((const uint4*)(pl + (size_t)q.y * 64) + lane8);
                const uint4 u2 = __ldg((const uint4*)(pl + (size_t)q.z * 64) + lane8);
                const uint4 u3 = __ldg((const uint4*)(pl + (size_t)q.w * 64) + lane8);
                const uint32_t* p0 = (const uint32_t*)&u0;
                const uint32_t* p1 = (const uint32_t*)&u1;
                const uint32_t* p2 = (const uint32_t*)&u2;
                const uint32_t* p3 = (const uint32_t*)&u3;
                uint4 st;
                uint32_t* s = (uint32_t*)&st;
                #pragma unroll
                for (int j = 0; j < 4; j++) {
                    const float2 f0 = __half22float2(*(const __half2*)&p0[j]);
                    const float2 f1 = __half22float2(*(const __half2*)&p1[j]);
                    const float2 f2 = __half22float2(*(const __half2*)&p2[j]);
                    const float2 f3 = __half22float2(*(const __half2*)&p3[j]);
                    float2 r;
                    r.x = w.x * f0.x + w.y * f1.x + w.z * f2.x + w.w * f3.x;
                    r.y = w.x * f0.y + w.y * f1.y + w.z * f2.y + w.w * f3.y;
                    const __half2 h = __float22half2_rn(r);
                    s[j] = *(const uint32_t*)&h;
                }
                *(uint4*)(vb + pix * (KPADH * 2) + lane8 * 16) = st;
            }
        }

        __syncthreads();

        // mma: per warp 32co x 64pix; 4 ksteps of k16; B via ldmatrix.x4
        #pragma unroll
        for (int ks = 0; ks < 4; ks++) {
            const int g = (c << 2) + ks;     // global k16 step 0..71
            const uint4 A0 = __ldg(&g_wfh[(g * 8 + mb0    ) * 32 + lane]);
            const uint4 A1 = __ldg(&g_wfh[(g * 8 + mb0 + 1) * 32 + lane]);
            #pragma unroll
            for (int p = 0; p < 4; p++) {
                const uint32_t addr = vb32
                    + (uint32_t)(n0 + p * 16 + lm_pix) * (KPADH * 2)
                    + (uint32_t)(ks * 16 + lm_k) * 2;
                uint32_t r0, r1, r2, r3;
                asm volatile(
                    "ldmatrix.sync.aligned.m8n8.x4.shared.b16 {%0,%1,%2,%3}, [%4];"
                    : "=r"(r0), "=r"(r1), "=r"(r2), "=r"(r3) : "r"(addr));
                mma_f16(acc[0][p * 2],     A0, r0, r1);
                mma_f16(acc[1][p * 2],     A1, r0, r1);
                mma_f16(acc[0][p * 2 + 1], A0, r2, r3);
                mma_f16(acc[1][p * 2 + 1], A1, r2, r3);
            }
        }
        // no trailing sync: gather(c+2) only happens after sync(c+1), and every
        // warp's mma(c) precedes sync(c+1) in program order.
    }

    // ---- 4. epilogue: bias + store ----
    #pragma unroll
    for (int mt = 0; mt < 2; mt++) {
        const int r0 = m0 + mt * 16 + grp;
        const int r1 = r0 + 8;
        const float bv0 = bias[r0];
        const float bv1 = bias[r1];
        float* o0 = out + ((size_t)(b * COUT + r0)) * HW + rp * 128 + n0 + 2 * t4;
        float* o1 = out + ((size_t)(b * COUT + r1)) * HW + rp * 128 + n0 + 2 * t4;
        #pragma unroll
        for (int nt = 0; nt < 8; nt++) {
            *(float2*)(o0 + nt * 8) = make_float2(acc[mt][nt][0] + bv0, acc[mt][nt][1] + bv0);
            *(float2*)(o1 + nt * 8) = make_float2(acc[mt][nt][2] + bv1, acc[mt][nt][3] + bv1);
        }
    }
}

// ---------------- launch ----------------
extern "C" void kernel_launch(void* const* d_in, const int* in_sizes, int n_in,
                              void* d_out, int out_size)
{
    const float* x      = (const float*)d_in[0];
    const float* offset = (const float*)d_in[1];
    const float* weight = (const float*)d_in[2];
    const float* bias   = (const float*)d_in[3];
    float* out = (float*)d_out;

    cudaFuncSetAttribute(deform_conv_mma_kernel,
                         cudaFuncAttributeMaxDynamicSharedMemorySize, SMEM_TOTAL);

    prep_all_kernel<<<2048 + 72, 256>>>(x, weight);
    deform_conv_mma_kernel<<<BB * 32, 256, SMEM_TOTAL>>>(offset, bias, out);
}